// round 7
// baseline (speedup 1.0000x reference)
#include <cuda_runtime.h>
#include <cuda_bf16.h>

#define FULL 0xffffffffu
#define MAXB 4096
#define FDIM 168   // 165 valid features, padded to 42 float4

// ---- device scratch (static: no allocation anywhere) ----
__device__ float g_scratch[MAXB * FDIM];   // per-row feature vector f
__device__ float g_G[FDIM * 64];           // folded weight matrix
__device__ float g_b1[64];                 // folded fc1 bias

// ============================================================
// K0: fold all linear post-pool ops into G[168x64], b1[64].
// f layout: [0:32) u_p  [32:64) u_c  [64:115) cnt_p  [115:165) cnt_c
// ============================================================
__global__ void k0_fold(const float* __restrict__ w_p2, const float* __restrict__ b_p2,
                        const float* __restrict__ w_c2, const float* __restrict__ b_c2,
                        const float* __restrict__ emb_gender, const float* __restrict__ emb_korean,
                        const float* __restrict__ emb_primary, const float* __restrict__ emb_job,
                        const float* __restrict__ emb_rep, const float* __restrict__ emb_place,
                        const float* __restrict__ emb_add,
                        const float* __restrict__ w_fc1, const float* __restrict__ b_fc1)
{
    const int gid = blockIdx.x * blockDim.x + threadIdx.x;
    if (gid >= 169 * 64) return;
    const int v = gid >> 6;
    const int j = gid & 63;

    if (v < 32) {                 // u_p @ w_p2 folded through w_fc1 rows 64..95
        float s = 0.f;
        #pragma unroll
        for (int d = 0; d < 32; d++)
            s = fmaf(w_p2[v * 32 + d], w_fc1[(64 + d) * 64 + j], s);
        g_G[v * 64 + j] = s;
    } else if (v < 64) {          // u_c @ w_c2 folded through w_fc1 rows 96..127
        const int e = v - 32;
        float s = 0.f;
        #pragma unroll
        for (int d = 0; d < 32; d++)
            s = fmaf(w_c2[e * 32 + d], w_fc1[(96 + d) * 64 + j], s);
        g_G[v * 64 + j] = s;
    } else if (v < 115) {         // cat_p embedding rows folded through w_fc1 rows 0..31
        const int vv = v - 64;
        const float* er;
        if      (vv < 2)  er = emb_gender  + vv * 32;
        else if (vv < 4)  er = emb_korean  + (vv - 2) * 32;
        else if (vv < 6)  er = emb_primary + (vv - 4) * 32;
        else if (vv < 17) er = emb_job     + (vv - 6) * 32;
        else              er = emb_rep     + (vv - 17) * 32;
        float s = 0.f;
        #pragma unroll
        for (int d = 0; d < 32; d++)
            s = fmaf(er[d], w_fc1[d * 64 + j], s);
        g_G[v * 64 + j] = s;
    } else if (v < 165) {         // cat_c embedding rows folded through w_fc1 rows 32..63
        const int cc = v - 115;
        const float* er = (cc < 19) ? (emb_place + cc * 32) : (emb_add + (cc - 19) * 32);
        float s = 0.f;
        #pragma unroll
        for (int d = 0; d < 32; d++)
            s = fmaf(er[d], w_fc1[(32 + d) * 64 + j], s);
        g_G[v * 64 + j] = s;
    } else if (v < FDIM) {        // padding rows
        g_G[v * 64 + j] = 0.f;
    } else {                      // v == 168: folded bias
        float s = b_fc1[j];
        #pragma unroll
        for (int d = 0; d < 32; d++) {
            s = fmaf(b_p2[d], w_fc1[(64 + d) * 64 + j], s);
            s = fmaf(b_c2[d], w_fc1[(96 + d) * 64 + j], s);
        }
        g_b1[j] = s;
    }
}

// ============================================================
// K1: mainloop only. One warp per row; histogram + relu-sum,
// prefetch depth 2; writes scaled feature vector to g_scratch.
// ============================================================
__device__ __forceinline__ void hupd(unsigned* hw, int base, int idx, int lane) {
    unsigned m = __match_any_sync(FULL, idx);
    int leader = __ffs(m) - 1;
    if (lane == leader && idx != 999) {
        hw[base + idx] += (unsigned)__popc(m);
    }
}

struct Tok {
    float p0, p1, p2, c0, c1;
    int i0, i1, i2, i3, i4, j0, j1;
};

__device__ __forceinline__ Tok loadtok(const float* __restrict__ cont_p,
                                       const float* __restrict__ cont_c,
                                       const int* __restrict__ cat_p,
                                       const int* __restrict__ cat_c,
                                       int rowbase, int t, bool valid) {
    Tok k;
    k.p0 = k.p1 = k.p2 = k.c0 = k.c1 = 0.f;
    k.i0 = k.i1 = k.i2 = k.i3 = k.i4 = k.j0 = k.j1 = 999;
    if (valid) {
        const float* cp = cont_p + (rowbase + t) * 3;
        k.p0 = cp[0]; k.p1 = cp[1]; k.p2 = cp[2];
        float2 cc = *reinterpret_cast<const float2*>(cont_c + (rowbase + t) * 2);
        k.c0 = cc.x; k.c1 = cc.y;
        const int* ip = cat_p + (rowbase + t) * 5;
        k.i0 = ip[0]; k.i1 = ip[1]; k.i2 = ip[2]; k.i3 = ip[3]; k.i4 = ip[4];
        int2 jc = *reinterpret_cast<const int2*>(cat_c + (rowbase + t) * 2);
        k.j0 = jc.x; k.j1 = jc.y;
    }
    return k;
}

__global__ void __launch_bounds__(128, 8)
k1_main(const float* __restrict__ cont_p, const float* __restrict__ cont_c,
        const int* __restrict__ cat_p, const int* __restrict__ cat_c,
        const int* __restrict__ lengths,
        const float* __restrict__ w_p1, const float* __restrict__ b_p1,
        const float* __restrict__ w_c1, const float* __restrict__ b_c1,
        int S, int B)
{
    // Histogram layout (101): gender@0(2) korean@2(2) primary@4(2) job@6(11)
    // rep@17(34) place@51(19) add@70(31)
    __shared__ float4   stX[4][2][32];   // (p0, c0, p1, c1)
    __shared__ float2   stY[4][2][32];   // (p2, 0)
    __shared__ unsigned hist_s[4][104];

    const int tid  = threadIdx.x;
    const int lane = tid & 31;
    const int w    = tid >> 5;
    const int row  = blockIdx.x * 4 + w;
    if (row >= B) return;

    const int len = lengths[row];
    const int rowbase = row * S;
    unsigned* hw = hist_s[w];
    for (int i = lane; i < 104; i += 32) hw[i] = 0u;

    // lane = channel d; first-layer weights in registers
    const float wp0 = w_p1[lane];
    const float wp1 = w_p1[32 + lane];
    const float wp2 = w_p1[64 + lane];
    const float bp  = b_p1[lane];
    const float wc0 = w_c1[lane];
    const float wc1 = w_c1[32 + lane];
    const float bc  = b_c1[lane];

    __syncwarp();

    float ap0 = 0.f, ap1 = 0.f, ac0 = 0.f, ac1 = 0.f;
    int t0 = 0, buf = 0;

    // Prefetch depth 2.
    Tok cur = loadtok(cont_p, cont_c, cat_p, cat_c, rowbase, lane, lane < len);
    Tok nxt = loadtok(cont_p, cont_c, cat_p, cat_c, rowbase, 32 + lane,
                      32 + lane < len);

    while (true) {
        const int nv = min(32, len - t0);

        // Stage current chunk + histogram it.
        stX[w][buf][lane] = make_float4(cur.p0, cur.c0, cur.p1, cur.c1);
        stY[w][buf][lane] = make_float2(cur.p2, 0.f);
        hupd(hw, 0,  cur.i0, lane);
        hupd(hw, 2,  cur.i1, lane);
        hupd(hw, 4,  cur.i2, lane);
        hupd(hw, 6,  cur.i3, lane);
        hupd(hw, 17, cur.i4, lane);
        hupd(hw, 51, cur.j0, lane);
        hupd(hw, 70, cur.j1, lane);

        // Prefetch chunk t0+64 (2 ahead) before consuming the stage.
        const int t2 = t0 + 64;
        const bool have_next = (t0 + 32) < len;
        Tok n2 = loadtok(cont_p, cont_c, cat_p, cat_c, rowbase, t2 + lane,
                         t2 + lane < len);
        __syncwarp();

        // Broadcast j-loop: 2 LDS + 5 FMA + 2 FMNMX + 2 FADD per token,
        // 2 tokens/iter with split accumulators.
        int j = 0;
        #pragma unroll 4
        for (; j + 2 <= nv; j += 2) {
            const float4 xA = stX[w][buf][j];
            const float2 yA = stY[w][buf][j];
            const float4 xB = stX[w][buf][j + 1];
            const float2 yB = stY[w][buf][j + 1];
            ap0 += fmaxf(fmaf(yA.x, wp2, fmaf(xA.z, wp1, fmaf(xA.x, wp0, bp))), 0.f);
            ac0 += fmaxf(fmaf(xA.w, wc1, fmaf(xA.y, wc0, bc)), 0.f);
            ap1 += fmaxf(fmaf(yB.x, wp2, fmaf(xB.z, wp1, fmaf(xB.x, wp0, bp))), 0.f);
            ac1 += fmaxf(fmaf(xB.w, wc1, fmaf(xB.y, wc0, bc)), 0.f);
        }
        if (j < nv) {
            const float4 xA = stX[w][buf][j];
            const float2 yA = stY[w][buf][j];
            ap0 += fmaxf(fmaf(yA.x, wp2, fmaf(xA.z, wp1, fmaf(xA.x, wp0, bp))), 0.f);
            ac0 += fmaxf(fmaf(xA.w, wc1, fmaf(xA.y, wc0, bc)), 0.f);
        }

        if (!have_next) break;
        cur = nxt;
        nxt = n2;
        t0 += 32;
        buf ^= 1;
    }

    // Write scaled feature vector f[168] (coalesced STG).
    const float invlen = 1.0f / (float)len;
    const float inv5   = invlen * 0.2f;
    const float inv2   = invlen * 0.5f;
    float* f = g_scratch + row * FDIM;
    f[lane]      = (ap0 + ap1) * invlen;
    f[32 + lane] = (ac0 + ac1) * invlen;
    #pragma unroll
    for (int i = lane; i < 104; i += 32) {
        f[64 + i] = (float)hw[i] * ((i < 51) ? inv5 : inv2);  // 101..103 are 0
    }
}

// ============================================================
// K2: dense balanced epilogue. One warp per row.
// out = relu( relu(f @ G + b1) @ w_fc2 + b_fc2 )
// ============================================================
__global__ void __launch_bounds__(128, 8)
k2_epi(const float* __restrict__ w_fc2, const float* __restrict__ b_fc2,
       float* __restrict__ out, int B)
{
    __shared__ float4 fbuf4[4][42];

    const int tid  = threadIdx.x;
    const int lane = tid & 31;
    const int w    = tid >> 5;
    const int row  = blockIdx.x * 4 + w;
    if (row >= B) return;

    // Cooperative load of this row's f into shared (42 float4 = 168 floats).
    const float4* src = reinterpret_cast<const float4*>(g_scratch + row * FDIM);
    fbuf4[w][lane] = src[lane];
    if (lane < 10) fbuf4[w][32 + lane] = src[32 + lane];
    __syncwarp();

    const float* fb = reinterpret_cast<const float*>(fbuf4[w]);
    const float* Gp = g_G + lane;

    float z0a = g_b1[lane], z0b = 0.f;
    float z1a = g_b1[32 + lane], z1b = 0.f;
    #pragma unroll 5
    for (int v = 0; v < 165; v += 2) {
        const float fv = fb[v];
        z0a = fmaf(fv, Gp[v * 64], z0a);
        z1a = fmaf(fv, Gp[v * 64 + 32], z1a);
        if (v + 1 < 165) {
            const float fw = fb[v + 1];
            z0b = fmaf(fw, Gp[(v + 1) * 64], z0b);
            z1b = fmaf(fw, Gp[(v + 1) * 64 + 32], z1b);
        }
    }
    const float h0 = fmaxf(z0a + z0b, 0.f);
    const float h1 = fmaxf(z1a + z1b, 0.f);

    // fc2: 64 -> 2, warp tree-reduce.
    float s0 = h0 * w_fc2[lane * 2]     + h1 * w_fc2[(32 + lane) * 2];
    float s1 = h0 * w_fc2[lane * 2 + 1] + h1 * w_fc2[(32 + lane) * 2 + 1];
    #pragma unroll
    for (int off = 16; off; off >>= 1) {
        s0 += __shfl_xor_sync(FULL, s0, off);
        s1 += __shfl_xor_sync(FULL, s1, off);
    }
    if (lane == 0) {
        float2 o;
        o.x = fmaxf(s0 + b_fc2[0], 0.f);
        o.y = fmaxf(s1 + b_fc2[1], 0.f);
        reinterpret_cast<float2*>(out)[row] = o;
    }
}

extern "C" void kernel_launch(void* const* d_in, const int* in_sizes, int n_in,
                              void* d_out, int out_size)
{
    const float* cont_p   = (const float*)d_in[0];
    const float* cont_c   = (const float*)d_in[1];
    const int*   cat_p    = (const int*)  d_in[2];
    const int*   cat_c    = (const int*)  d_in[3];
    const int*   lengths  = (const int*)  d_in[4];
    const float* w_p1     = (const float*)d_in[5];
    const float* b_p1     = (const float*)d_in[6];
    const float* w_p2     = (const float*)d_in[7];
    const float* b_p2     = (const float*)d_in[8];
    const float* w_c1     = (const float*)d_in[9];
    const float* b_c1     = (const float*)d_in[10];
    const float* w_c2     = (const float*)d_in[11];
    const float* b_c2     = (const float*)d_in[12];
    const float* emb_gender  = (const float*)d_in[13];
    const float* emb_korean  = (const float*)d_in[14];
    const float* emb_primary = (const float*)d_in[15];
    const float* emb_job     = (const float*)d_in[16];
    const float* emb_rep     = (const float*)d_in[17];
    const float* emb_place   = (const float*)d_in[18];
    const float* emb_add     = (const float*)d_in[19];
    const float* w_fc1    = (const float*)d_in[20];
    const float* b_fc1    = (const float*)d_in[21];
    const float* w_fc2    = (const float*)d_in[22];
    const float* b_fc2    = (const float*)d_in[23];
    float* out = (float*)d_out;

    const int B = in_sizes[4];                 // lengths: [B]
    const int S = in_sizes[0] / (B * 3);       // cont_p: [B,S,3]
    const int grid = (B + 3) / 4;              // one warp per row

    k0_fold<<<(169 * 64 + 127) / 128, 128>>>(w_p2, b_p2, w_c2, b_c2,
                                             emb_gender, emb_korean, emb_primary,
                                             emb_job, emb_rep, emb_place, emb_add,
                                             w_fc1, b_fc1);
    k1_main<<<grid, 128>>>(cont_p, cont_c, cat_p, cat_c, lengths,
                           w_p1, b_p1, w_c1, b_c1, S, B);
    k2_epi<<<grid, 128>>>(w_fc2, b_fc2, out, B);
}

// round 10
// speedup vs baseline: 1.0173x; 1.0173x over previous
#include <cuda_runtime.h>
#include <cuda_bf16.h>

#define FULL 0xffffffffu
#define MAXB 4096
#define FDIM 168   // [0:32) accp | [32:64) accc | [64:165) counts | pad

// ---- device scratch (static: no allocation anywhere) ----
__device__ float g_accum[MAXB * FDIM];

// ============================================================
// kA: one warp per (row, chunk). Histogram + relu-sum for ONE
// 32-token chunk, reduced into g_accum via RED.ADD.
// Count layout (101): gender@0(2) korean@2(2) primary@4(2)
// job@6(11) rep@17(34) place@51(19) add@70(31)
// ============================================================
__device__ __forceinline__ void hupd_g(float* fr, int base, int idx, int lane) {
    unsigned m = __match_any_sync(FULL, idx);
    int leader = __ffs(m) - 1;
    if (lane == leader && idx != 999) {
        atomicAdd(fr + base + idx, (float)__popc(m));
    }
}

__global__ void __launch_bounds__(256)
ka_chunks(const float* __restrict__ cont_p, const float* __restrict__ cont_c,
          const int* __restrict__ cat_p, const int* __restrict__ cat_c,
          const int* __restrict__ lengths,
          const float* __restrict__ w_p1, const float* __restrict__ b_p1,
          const float* __restrict__ w_c1, const float* __restrict__ b_c1,
          int S, int B, int smax)
{
    __shared__ float4 stX[8][32];   // (p0, c0, p1, c1)
    __shared__ float2 stY[8][32];   // (p2, 0)

    const int lane = threadIdx.x & 31;
    const int wib  = threadIdx.x >> 5;               // warp in block
    const int g    = blockIdx.x * 8 + wib;           // global warp id
    const int row  = g / smax;
    const int chunk = g - row * smax;
    if (row >= B) return;

    const int len = lengths[row];
    const int t0  = chunk * 32;
    if (t0 >= len) return;                           // dead chunk: exit fast

    const int nv = min(32, len - t0);
    const bool valid = lane < nv;
    const int rowbase = row * S;
    const int t = t0 + lane;

    // Per-lane AoS token load.
    float p0 = 0.f, p1 = 0.f, p2 = 0.f, c0 = 0.f, c1 = 0.f;
    int i0 = 999, i1 = 999, i2 = 999, i3 = 999, i4 = 999, j0 = 999, j1 = 999;
    if (valid) {
        const float* cp = cont_p + (rowbase + t) * 3;
        p0 = cp[0]; p1 = cp[1]; p2 = cp[2];
        float2 cc = *reinterpret_cast<const float2*>(cont_c + (rowbase + t) * 2);
        c0 = cc.x; c1 = cc.y;
        const int* ip = cat_p + (rowbase + t) * 5;
        i0 = ip[0]; i1 = ip[1]; i2 = ip[2]; i3 = ip[3]; i4 = ip[4];
        int2 jc = *reinterpret_cast<const int2*>(cat_c + (rowbase + t) * 2);
        j0 = jc.x; j1 = jc.y;
    }

    // Stage for broadcast consumption.
    stX[wib][lane] = make_float4(p0, c0, p1, c1);
    stY[wib][lane] = make_float2(p2, 0.f);

    float* fr = g_accum + row * FDIM;

    // Histogram counts straight to global (RED.ADD, no return).
    hupd_g(fr, 64 +  0, i0, lane);
    hupd_g(fr, 64 +  2, i1, lane);
    hupd_g(fr, 64 +  4, i2, lane);
    hupd_g(fr, 64 +  6, i3, lane);
    hupd_g(fr, 64 + 17, i4, lane);
    hupd_g(fr, 64 + 51, j0, lane);
    hupd_g(fr, 64 + 70, j1, lane);

    // lane = channel d; first-layer weights in registers.
    const float wp0 = w_p1[lane];
    const float wp1 = w_p1[32 + lane];
    const float wp2 = w_p1[64 + lane];
    const float bp  = b_p1[lane];
    const float wc0 = w_c1[lane];
    const float wc1 = w_c1[32 + lane];
    const float bc  = b_c1[lane];

    __syncwarp();

    // Broadcast j-loop: 2 LDS + 5 FMA + 2 FMNMX + 2 FADD per token.
    float ap0 = 0.f, ap1 = 0.f, ac0 = 0.f, ac1 = 0.f;
    int j = 0;
    #pragma unroll 4
    for (; j + 2 <= nv; j += 2) {
        const float4 xA = stX[wib][j];
        const float2 yA = stY[wib][j];
        const float4 xB = stX[wib][j + 1];
        const float2 yB = stY[wib][j + 1];
        ap0 += fmaxf(fmaf(yA.x, wp2, fmaf(xA.z, wp1, fmaf(xA.x, wp0, bp))), 0.f);
        ac0 += fmaxf(fmaf(xA.w, wc1, fmaf(xA.y, wc0, bc)), 0.f);
        ap1 += fmaxf(fmaf(yB.x, wp2, fmaf(xB.z, wp1, fmaf(xB.x, wp0, bp))), 0.f);
        ac1 += fmaxf(fmaf(xB.w, wc1, fmaf(xB.y, wc0, bc)), 0.f);
    }
    if (j < nv) {
        const float4 xA = stX[wib][j];
        const float2 yA = stY[wib][j];
        ap0 += fmaxf(fmaf(yA.x, wp2, fmaf(xA.z, wp1, fmaf(xA.x, wp0, bp))), 0.f);
        ac0 += fmaxf(fmaf(xA.w, wc1, fmaf(xA.y, wc0, bc)), 0.f);
    }

    atomicAdd(fr + lane,      ap0 + ap1);
    atomicAdd(fr + 32 + lane, ac0 + ac1);
}

// ============================================================
// kB: warp-per-row epilogue (uniform work per row).
// ============================================================
__global__ void __launch_bounds__(128)
kb_epi(const int* __restrict__ lengths,
       const float* __restrict__ w_p2, const float* __restrict__ b_p2,
       const float* __restrict__ w_c2, const float* __restrict__ b_c2,
       const float* __restrict__ emb_gender, const float* __restrict__ emb_korean,
       const float* __restrict__ emb_primary, const float* __restrict__ emb_job,
       const float* __restrict__ emb_rep, const float* __restrict__ emb_place,
       const float* __restrict__ emb_add,
       const float* __restrict__ w_fc1, const float* __restrict__ b_fc1,
       const float* __restrict__ w_fc2, const float* __restrict__ b_fc2,
       float* __restrict__ out, int B)
{
    __shared__ float4 xb4[4][32];   // pooled vector [ep | ec | hp | hc]

    const int tid  = threadIdx.x;
    const int lane = tid & 31;
    const int w    = tid >> 5;
    const int row  = blockIdx.x * 4 + w;
    if (row >= B) return;

    const float* fr = g_accum + row * FDIM;
    const float* cw = fr + 64;                 // count block (broadcast reads)
    const float invlen = 1.0f / (float)lengths[row];
    const int d = lane;

    // Second linears: broadcast pooled pre-activations via SHFL.
    const float up = fr[d] * invlen;
    const float uc = fr[32 + d] * invlen;
    float hp = b_p2[d], hc = b_c2[d];
    #pragma unroll
    for (int e = 0; e < 32; e++) {
        hp = fmaf(__shfl_sync(FULL, up, e), w_p2[e * 32 + d], hp);
        hc = fmaf(__shfl_sync(FULL, uc, e), w_c2[e * 32 + d], hc);
    }

    // Embedding means from counts (2 accumulators for ILP).
    float sa = 0.f, sb = 0.f;
    #pragma unroll
    for (int v = 0; v < 2; v++)  sa = fmaf(cw[v],      emb_gender[v * 32 + d], sa);
    #pragma unroll
    for (int v = 0; v < 2; v++)  sb = fmaf(cw[2 + v],  emb_korean[v * 32 + d], sb);
    #pragma unroll
    for (int v = 0; v < 2; v++)  sa = fmaf(cw[4 + v],  emb_primary[v * 32 + d], sa);
    #pragma unroll
    for (int v = 0; v < 11; v++) {
        if (v & 1) sb = fmaf(cw[6 + v], emb_job[v * 32 + d], sb);
        else       sa = fmaf(cw[6 + v], emb_job[v * 32 + d], sa);
    }
    #pragma unroll
    for (int v = 0; v < 34; v++) {
        if (v & 1) sb = fmaf(cw[17 + v], emb_rep[v * 32 + d], sb);
        else       sa = fmaf(cw[17 + v], emb_rep[v * 32 + d], sa);
    }
    const float ep = (sa + sb) * invlen * 0.2f;

    float ta = 0.f, tb = 0.f;
    #pragma unroll
    for (int v = 0; v < 19; v++) {
        if (v & 1) tb = fmaf(cw[51 + v], emb_place[v * 32 + d], tb);
        else       ta = fmaf(cw[51 + v], emb_place[v * 32 + d], ta);
    }
    #pragma unroll
    for (int v = 0; v < 31; v++) {
        if (v & 1) tb = fmaf(cw[70 + v], emb_add[v * 32 + d], tb);
        else       ta = fmaf(cw[70 + v], emb_add[v * 32 + d], ta);
    }
    const float ec = (ta + tb) * invlen * 0.5f;

    // Stage pooled vector x = [ep | ec | hp | hc] in warp-private shared.
    float* xb = reinterpret_cast<float*>(xb4[w]);
    xb[d] = ep; xb[32 + d] = ec; xb[64 + d] = hp; xb[96 + d] = hc;
    __syncwarp();

    // fc1: 128 -> 64 (2 outputs per lane); x via float4 LDS, split accumulators.
    float a0a = b_fc1[d],      a0b = 0.f;
    float a1a = b_fc1[32 + d], a1b = 0.f;
    #pragma unroll 8
    for (int i = 0; i < 128; i += 4) {
        const float4 xv = xb4[w][i >> 2];
        a0a = fmaf(xv.x, w_fc1[i * 64 + d], a0a);
        a1a = fmaf(xv.x, w_fc1[i * 64 + 32 + d], a1a);
        a0b = fmaf(xv.y, w_fc1[(i + 1) * 64 + d], a0b);
        a1b = fmaf(xv.y, w_fc1[(i + 1) * 64 + 32 + d], a1b);
        a0a = fmaf(xv.z, w_fc1[(i + 2) * 64 + d], a0a);
        a1a = fmaf(xv.z, w_fc1[(i + 2) * 64 + 32 + d], a1a);
        a0b = fmaf(xv.w, w_fc1[(i + 3) * 64 + d], a0b);
        a1b = fmaf(xv.w, w_fc1[(i + 3) * 64 + 32 + d], a1b);
    }
    const float h0 = fmaxf(a0a + a0b, 0.f);
    const float h1 = fmaxf(a1a + a1b, 0.f);

    // fc2: 64 -> 2, warp tree-reduce.
    float s0 = h0 * w_fc2[d * 2]     + h1 * w_fc2[(32 + d) * 2];
    float s1 = h0 * w_fc2[d * 2 + 1] + h1 * w_fc2[(32 + d) * 2 + 1];
    #pragma unroll
    for (int off = 16; off; off >>= 1) {
        s0 += __shfl_xor_sync(FULL, s0, off);
        s1 += __shfl_xor_sync(FULL, s1, off);
    }
    if (lane == 0) {
        float2 o;
        o.x = fmaxf(s0 + b_fc2[0], 0.f);
        o.y = fmaxf(s1 + b_fc2[1], 0.f);
        reinterpret_cast<float2*>(out)[row] = o;
    }
}

extern "C" void kernel_launch(void* const* d_in, const int* in_sizes, int n_in,
                              void* d_out, int out_size)
{
    const float* cont_p   = (const float*)d_in[0];
    const float* cont_c   = (const float*)d_in[1];
    const int*   cat_p    = (const int*)  d_in[2];
    const int*   cat_c    = (const int*)  d_in[3];
    const int*   lengths  = (const int*)  d_in[4];
    const float* w_p1     = (const float*)d_in[5];
    const float* b_p1     = (const float*)d_in[6];
    const float* w_p2     = (const float*)d_in[7];
    const float* b_p2     = (const float*)d_in[8];
    const float* w_c1     = (const float*)d_in[9];
    const float* b_c1     = (const float*)d_in[10];
    const float* w_c2     = (const float*)d_in[11];
    const float* b_c2     = (const float*)d_in[12];
    const float* emb_gender  = (const float*)d_in[13];
    const float* emb_korean  = (const float*)d_in[14];
    const float* emb_primary = (const float*)d_in[15];
    const float* emb_job     = (const float*)d_in[16];
    const float* emb_rep     = (const float*)d_in[17];
    const float* emb_place   = (const float*)d_in[18];
    const float* emb_add     = (const float*)d_in[19];
    const float* w_fc1    = (const float*)d_in[20];
    const float* b_fc1    = (const float*)d_in[21];
    const float* w_fc2    = (const float*)d_in[22];
    const float* b_fc2    = (const float*)d_in[23];
    float* out = (float*)d_out;

    const int B = in_sizes[4];                 // lengths: [B]
    const int S = in_sizes[0] / (B * 3);       // cont_p: [B,S,3]
    const int smax = (S + 31) / 32;            // chunks per row (8 for S=256)

    // Zero accumulators via async memset (graph-capturable, no allocation).
    void* accum_ptr = nullptr;
    cudaGetSymbolAddress(&accum_ptr, g_accum);
    cudaMemsetAsync(accum_ptr, 0, (size_t)B * FDIM * sizeof(float));

    // kA: one warp per (row, chunk).
    const int nwarp = B * smax;
    ka_chunks<<<(nwarp + 7) / 8, 256>>>(cont_p, cont_c, cat_p, cat_c, lengths,
                                        w_p1, b_p1, w_c1, b_c1, S, B, smax);

    // kB: warp-per-row epilogue.
    kb_epi<<<(B + 3) / 4, 128>>>(lengths, w_p2, b_p2, w_c2, b_c2,
                                 emb_gender, emb_korean, emb_primary, emb_job,
                                 emb_rep, emb_place, emb_add,
                                 w_fc1, b_fc1, w_fc2, b_fc2, out, B);
}

// round 11
// speedup vs baseline: 1.1786x; 1.1585x over previous
#include <cuda_runtime.h>
#include <cuda_bf16.h>

#define FULL 0xffffffffu
#define MAXB 4096
#define FDIM 168   // [0:32) accp | [32:64) accc | [64:165) counts | pad

// ---- device scratch (static: no allocation anywhere) ----
__device__ float g_accum[MAXB * FDIM];
__device__ float g_G[FDIM * 64];     // folded weight matrix
__device__ float g_b1[64];           // folded fc1 bias

// ============================================================
// Fold (runs in kA's trailing blocks): G[168x64], b1[64].
// f layout: [0:32) u_p | [32:64) u_c | [64:115) cnt_p | [115:165) cnt_c
// ============================================================
__device__ void fold_work(int gid,
                          const float* __restrict__ w_p2, const float* __restrict__ b_p2,
                          const float* __restrict__ w_c2, const float* __restrict__ b_c2,
                          const float* __restrict__ emb_gender, const float* __restrict__ emb_korean,
                          const float* __restrict__ emb_primary, const float* __restrict__ emb_job,
                          const float* __restrict__ emb_rep, const float* __restrict__ emb_place,
                          const float* __restrict__ emb_add,
                          const float* __restrict__ w_fc1, const float* __restrict__ b_fc1)
{
    if (gid >= 169 * 64) return;
    const int v = gid >> 6;
    const int j = gid & 63;

    if (v < 32) {                 // u_p @ w_p2 folded through w_fc1 rows 64..95
        float s = 0.f;
        #pragma unroll
        for (int d = 0; d < 32; d++)
            s = fmaf(w_p2[v * 32 + d], w_fc1[(64 + d) * 64 + j], s);
        g_G[v * 64 + j] = s;
    } else if (v < 64) {          // u_c @ w_c2 folded through w_fc1 rows 96..127
        const int e = v - 32;
        float s = 0.f;
        #pragma unroll
        for (int d = 0; d < 32; d++)
            s = fmaf(w_c2[e * 32 + d], w_fc1[(96 + d) * 64 + j], s);
        g_G[v * 64 + j] = s;
    } else if (v < 115) {         // cat_p embedding rows through w_fc1 rows 0..31
        const int vv = v - 64;
        const float* er;
        if      (vv < 2)  er = emb_gender  + vv * 32;
        else if (vv < 4)  er = emb_korean  + (vv - 2) * 32;
        else if (vv < 6)  er = emb_primary + (vv - 4) * 32;
        else if (vv < 17) er = emb_job     + (vv - 6) * 32;
        else              er = emb_rep     + (vv - 17) * 32;
        float s = 0.f;
        #pragma unroll
        for (int d = 0; d < 32; d++)
            s = fmaf(er[d], w_fc1[d * 64 + j], s);
        g_G[v * 64 + j] = s;
    } else if (v < 165) {         // cat_c embedding rows through w_fc1 rows 32..63
        const int cc = v - 115;
        const float* er = (cc < 19) ? (emb_place + cc * 32) : (emb_add + (cc - 19) * 32);
        float s = 0.f;
        #pragma unroll
        for (int d = 0; d < 32; d++)
            s = fmaf(er[d], w_fc1[(32 + d) * 64 + j], s);
        g_G[v * 64 + j] = s;
    } else if (v < FDIM) {        // padding rows
        g_G[v * 64 + j] = 0.f;
    } else {                      // v == 168: folded bias
        float s = b_fc1[j];
        #pragma unroll
        for (int d = 0; d < 32; d++) {
            s = fmaf(b_p2[d], w_fc1[(64 + d) * 64 + j], s);
            s = fmaf(b_c2[d], w_fc1[(96 + d) * 64 + j], s);
        }
        g_b1[j] = s;
    }
}

// ============================================================
// kA: one warp per (row, chunk), RED.ADD into g_accum.
// Count layout (101): gender@0(2) korean@2(2) primary@4(2)
// job@6(11) rep@17(34) place@51(19) add@70(31)
// Trailing blocks run fold_work instead.
// ============================================================
__device__ __forceinline__ void hupd_g(float* fr, int base, int idx, int lane) {
    unsigned m = __match_any_sync(FULL, idx);
    int leader = __ffs(m) - 1;
    if (lane == leader && idx != 999) {
        atomicAdd(fr + base + idx, (float)__popc(m));
    }
}

__global__ void __launch_bounds__(256)
ka_chunks(const float* __restrict__ cont_p, const float* __restrict__ cont_c,
          const int* __restrict__ cat_p, const int* __restrict__ cat_c,
          const int* __restrict__ lengths,
          const float* __restrict__ w_p1, const float* __restrict__ b_p1,
          const float* __restrict__ w_c1, const float* __restrict__ b_c1,
          const float* __restrict__ w_p2, const float* __restrict__ b_p2,
          const float* __restrict__ w_c2, const float* __restrict__ b_c2,
          const float* __restrict__ emb_gender, const float* __restrict__ emb_korean,
          const float* __restrict__ emb_primary, const float* __restrict__ emb_job,
          const float* __restrict__ emb_rep, const float* __restrict__ emb_place,
          const float* __restrict__ emb_add,
          const float* __restrict__ w_fc1, const float* __restrict__ b_fc1,
          int S, int B, int smax, int chunkBlocks)
{
    __shared__ float4 stX[8][32];   // (p0, c0, p1, c1)
    __shared__ float2 stY[8][32];   // (p2, 0)

    if (blockIdx.x >= chunkBlocks) {
        const int gid = (blockIdx.x - chunkBlocks) * 256 + threadIdx.x;
        fold_work(gid, w_p2, b_p2, w_c2, b_c2,
                  emb_gender, emb_korean, emb_primary, emb_job, emb_rep,
                  emb_place, emb_add, w_fc1, b_fc1);
        return;
    }

    const int lane = threadIdx.x & 31;
    const int wib  = threadIdx.x >> 5;
    const int g    = blockIdx.x * 8 + wib;
    const int row  = g / smax;
    const int chunk = g - row * smax;
    if (row >= B) return;

    const int len = lengths[row];
    const int t0  = chunk * 32;
    if (t0 >= len) return;                           // dead chunk: fast exit

    const int nv = min(32, len - t0);
    const bool valid = lane < nv;
    const int rowbase = row * S;
    const int t = t0 + lane;

    float p0 = 0.f, p1 = 0.f, p2 = 0.f, c0 = 0.f, c1 = 0.f;
    int i0 = 999, i1 = 999, i2 = 999, i3 = 999, i4 = 999, j0 = 999, j1 = 999;
    if (valid) {
        const float* cp = cont_p + (rowbase + t) * 3;
        p0 = cp[0]; p1 = cp[1]; p2 = cp[2];
        float2 cc = *reinterpret_cast<const float2*>(cont_c + (rowbase + t) * 2);
        c0 = cc.x; c1 = cc.y;
        const int* ip = cat_p + (rowbase + t) * 5;
        i0 = ip[0]; i1 = ip[1]; i2 = ip[2]; i3 = ip[3]; i4 = ip[4];
        int2 jc = *reinterpret_cast<const int2*>(cat_c + (rowbase + t) * 2);
        j0 = jc.x; j1 = jc.y;
    }

    stX[wib][lane] = make_float4(p0, c0, p1, c1);
    stY[wib][lane] = make_float2(p2, 0.f);

    float* fr = g_accum + row * FDIM;

    hupd_g(fr, 64 +  0, i0, lane);
    hupd_g(fr, 64 +  2, i1, lane);
    hupd_g(fr, 64 +  4, i2, lane);
    hupd_g(fr, 64 +  6, i3, lane);
    hupd_g(fr, 64 + 17, i4, lane);
    hupd_g(fr, 64 + 51, j0, lane);
    hupd_g(fr, 64 + 70, j1, lane);

    const float wp0 = w_p1[lane];
    const float wp1 = w_p1[32 + lane];
    const float wp2 = w_p1[64 + lane];
    const float bp  = b_p1[lane];
    const float wc0 = w_c1[lane];
    const float wc1 = w_c1[32 + lane];
    const float bc  = b_c1[lane];

    __syncwarp();

    float ap0 = 0.f, ap1 = 0.f, ac0 = 0.f, ac1 = 0.f;
    int j = 0;
    #pragma unroll 4
    for (; j + 2 <= nv; j += 2) {
        const float4 xA = stX[wib][j];
        const float2 yA = stY[wib][j];
        const float4 xB = stX[wib][j + 1];
        const float2 yB = stY[wib][j + 1];
        ap0 += fmaxf(fmaf(yA.x, wp2, fmaf(xA.z, wp1, fmaf(xA.x, wp0, bp))), 0.f);
        ac0 += fmaxf(fmaf(xA.w, wc1, fmaf(xA.y, wc0, bc)), 0.f);
        ap1 += fmaxf(fmaf(yB.x, wp2, fmaf(xB.z, wp1, fmaf(xB.x, wp0, bp))), 0.f);
        ac1 += fmaxf(fmaf(xB.w, wc1, fmaf(xB.y, wc0, bc)), 0.f);
    }
    if (j < nv) {
        const float4 xA = stX[wib][j];
        const float2 yA = stY[wib][j];
        ap0 += fmaxf(fmaf(yA.x, wp2, fmaf(xA.z, wp1, fmaf(xA.x, wp0, bp))), 0.f);
        ac0 += fmaxf(fmaf(xA.w, wc1, fmaf(xA.y, wc0, bc)), 0.f);
    }

    atomicAdd(fr + lane,      ap0 + ap1);
    atomicAdd(fr + 32 + lane, ac0 + ac1);
}

// ============================================================
// kC: tiled GEMM epilogue. 32 rows/block, 256 threads.
// out = relu( relu(F @ G + b1) @ w_fc2 + b_fc2 )
// F loaded from g_accum with per-segment scaling.
// ============================================================
__global__ void __launch_bounds__(256)
kc_gemm(const int* __restrict__ lengths,
        const float* __restrict__ w_fc2, const float* __restrict__ b_fc2,
        float* __restrict__ out, int B)
{
    __shared__ float Fs[32][FDIM];   // 21504 B
    __shared__ float Gs[84][64];     // 21504 B (two-phase reuse)
    __shared__ float b1s[64];

    const int tid  = threadIdx.x;
    const int row0 = blockIdx.x * 32;

    // Load F tile with scale-on-load (invlen / invlen*0.2 / invlen*0.5).
    const float4* src = reinterpret_cast<const float4*>(g_accum + (size_t)row0 * FDIM);
    for (int idx = tid; idx < 32 * (FDIM / 4); idx += 256) {
        const int r   = idx / (FDIM / 4);
        const int kk4 = idx - r * (FDIM / 4);
        const int row = row0 + r;
        float4 v = make_float4(0.f, 0.f, 0.f, 0.f);
        float il = 0.f;
        if (row < B) {
            v = src[idx];
            il = 1.0f / (float)lengths[row];
        }
        const int kb = kk4 * 4;
        const float s0 = (kb + 0 < 64) ? il : ((kb + 0 < 115) ? il * 0.2f : il * 0.5f);
        const float s1 = (kb + 1 < 64) ? il : ((kb + 1 < 115) ? il * 0.2f : il * 0.5f);
        const float s2 = (kb + 2 < 64) ? il : ((kb + 2 < 115) ? il * 0.2f : il * 0.5f);
        const float s3 = (kb + 3 < 64) ? il : ((kb + 3 < 115) ? il * 0.2f : il * 0.5f);
        Fs[r][kb + 0] = v.x * s0;
        Fs[r][kb + 1] = v.y * s1;
        Fs[r][kb + 2] = v.z * s2;
        Fs[r][kb + 3] = v.w * s3;
    }
    if (tid < 64) b1s[tid] = g_b1[tid];

    // Thread tile: 2 rows x 4 cols.
    const int colg = tid & 15;            // cols j = colg*4 .. colg*4+3
    const int rp   = tid >> 4;            // row pair
    const int r0   = rp * 2, r1 = r0 + 1;

    float a00 = 0.f, a01 = 0.f, a02 = 0.f, a03 = 0.f;
    float a10 = 0.f, a11 = 0.f, a12 = 0.f, a13 = 0.f;

    #pragma unroll
    for (int ph = 0; ph < 2; ph++) {
        __syncthreads();   // ph0: Fs ready; ph1: Gs consumers done
        const float4* gsrc = reinterpret_cast<const float4*>(g_G + ph * 84 * 64);
        for (int idx = tid; idx < 84 * 16; idx += 256)
            reinterpret_cast<float4*>(&Gs[0][0])[idx] = gsrc[idx];
        __syncthreads();

        const int kof = ph * 84;
        #pragma unroll 4
        for (int kk = 0; kk < 84; kk++) {
            const float f0 = Fs[r0][kof + kk];
            const float f1 = Fs[r1][kof + kk];
            const float4 gv = *reinterpret_cast<const float4*>(&Gs[kk][colg * 4]);
            a00 = fmaf(f0, gv.x, a00);
            a01 = fmaf(f0, gv.y, a01);
            a02 = fmaf(f0, gv.z, a02);
            a03 = fmaf(f0, gv.w, a03);
            a10 = fmaf(f1, gv.x, a10);
            a11 = fmaf(f1, gv.y, a11);
            a12 = fmaf(f1, gv.z, a12);
            a13 = fmaf(f1, gv.w, a13);
        }
    }

    // Bias + relu -> H, then fc2 partials for this thread's 4 cols.
    const float bj0 = b1s[colg * 4 + 0];
    const float bj1 = b1s[colg * 4 + 1];
    const float bj2 = b1s[colg * 4 + 2];
    const float bj3 = b1s[colg * 4 + 3];
    const float h00 = fmaxf(a00 + bj0, 0.f), h01 = fmaxf(a01 + bj1, 0.f);
    const float h02 = fmaxf(a02 + bj2, 0.f), h03 = fmaxf(a03 + bj3, 0.f);
    const float h10 = fmaxf(a10 + bj0, 0.f), h11 = fmaxf(a11 + bj1, 0.f);
    const float h12 = fmaxf(a12 + bj2, 0.f), h13 = fmaxf(a13 + bj3, 0.f);

    // w_fc2 is [64][2] row-major: thread's 4 j's = 8 consecutive floats.
    const float4* w2 = reinterpret_cast<const float4*>(w_fc2 + colg * 8);
    const float4 w2a = w2[0];   // (j0o0, j0o1, j1o0, j1o1)
    const float4 w2b = w2[1];   // (j2o0, j2o1, j3o0, j3o1)

    float s0r0 = h00 * w2a.x + h01 * w2a.z + h02 * w2b.x + h03 * w2b.z;
    float s1r0 = h00 * w2a.y + h01 * w2a.w + h02 * w2b.y + h03 * w2b.w;
    float s0r1 = h10 * w2a.x + h11 * w2a.z + h12 * w2b.x + h13 * w2b.z;
    float s1r1 = h10 * w2a.y + h11 * w2a.w + h12 * w2b.y + h13 * w2b.w;

    // Reduce across 16 col groups (lane bits 0-3; bit 4 separates row pairs).
    #pragma unroll
    for (int m = 1; m <= 8; m <<= 1) {
        s0r0 += __shfl_xor_sync(FULL, s0r0, m);
        s1r0 += __shfl_xor_sync(FULL, s1r0, m);
        s0r1 += __shfl_xor_sync(FULL, s0r1, m);
        s1r1 += __shfl_xor_sync(FULL, s1r1, m);
    }

    if ((tid & 15) == 0) {   // lane 0 and lane 16 of each warp
        const float bo0 = b_fc2[0], bo1 = b_fc2[1];
        const int rowA = row0 + r0;
        const int rowB = row0 + r1;
        if (rowA < B) {
            float2 o;
            o.x = fmaxf(s0r0 + bo0, 0.f);
            o.y = fmaxf(s1r0 + bo1, 0.f);
            reinterpret_cast<float2*>(out)[rowA] = o;
        }
        if (rowB < B) {
            float2 o;
            o.x = fmaxf(s0r1 + bo0, 0.f);
            o.y = fmaxf(s1r1 + bo1, 0.f);
            reinterpret_cast<float2*>(out)[rowB] = o;
        }
    }
}

extern "C" void kernel_launch(void* const* d_in, const int* in_sizes, int n_in,
                              void* d_out, int out_size)
{
    const float* cont_p   = (const float*)d_in[0];
    const float* cont_c   = (const float*)d_in[1];
    const int*   cat_p    = (const int*)  d_in[2];
    const int*   cat_c    = (const int*)  d_in[3];
    const int*   lengths  = (const int*)  d_in[4];
    const float* w_p1     = (const float*)d_in[5];
    const float* b_p1     = (const float*)d_in[6];
    const float* w_p2     = (const float*)d_in[7];
    const float* b_p2     = (const float*)d_in[8];
    const float* w_c1     = (const float*)d_in[9];
    const float* b_c1     = (const float*)d_in[10];
    const float* w_c2     = (const float*)d_in[11];
    const float* b_c2     = (const float*)d_in[12];
    const float* emb_gender  = (const float*)d_in[13];
    const float* emb_korean  = (const float*)d_in[14];
    const float* emb_primary = (const float*)d_in[15];
    const float* emb_job     = (const float*)d_in[16];
    const float* emb_rep     = (const float*)d_in[17];
    const float* emb_place   = (const float*)d_in[18];
    const float* emb_add     = (const float*)d_in[19];
    const float* w_fc1    = (const float*)d_in[20];
    const float* b_fc1    = (const float*)d_in[21];
    const float* w_fc2    = (const float*)d_in[22];
    const float* b_fc2    = (const float*)d_in[23];
    float* out = (float*)d_out;

    const int B = in_sizes[4];                 // lengths: [B]
    const int S = in_sizes[0] / (B * 3);       // cont_p: [B,S,3]
    const int smax = (S + 31) / 32;            // chunks per row

    // Zero accumulators (graph-capturable async memset, no allocation).
    void* accum_ptr = nullptr;
    cudaGetSymbolAddress(&accum_ptr, g_accum);
    cudaMemsetAsync(accum_ptr, 0, (size_t)B * FDIM * sizeof(float));

    // kA: chunk blocks + fold blocks in one launch.
    const int chunkBlocks = (B * smax + 7) / 8;
    const int foldBlocks  = (169 * 64 + 255) / 256;
    ka_chunks<<<chunkBlocks + foldBlocks, 256>>>(
        cont_p, cont_c, cat_p, cat_c, lengths,
        w_p1, b_p1, w_c1, b_c1,
        w_p2, b_p2, w_c2, b_c2,
        emb_gender, emb_korean, emb_primary, emb_job, emb_rep,
        emb_place, emb_add, w_fc1, b_fc1,
        S, B, smax, chunkBlocks);

    // kC: tiled GEMM epilogue.
    kc_gemm<<<(B + 31) / 32, 256>>>(lengths, w_fc2, b_fc2, out, B);
}